// round 14
// baseline (speedup 1.0000x reference)
#include <cuda_runtime.h>
#include <cuda_bf16.h>
#include <cuda_fp16.h>
#include <math.h>
#include <stdint.h>

#define NN_MAX 50000
#define E_MAX  800000

// ---------------- scratch (device globals; no allocation) ----------------
__device__ __half   g_xwh[NN_MAX * 128];   // GEMM output rows, fp16 (gather input)
__device__ __half   g_x2 [NN_MAX * 128];   // layer-1 output, fp16 (GEMM2 A input)
__device__ float    g_as1 [NN_MAX * 4];
__device__ float    g_ad1 [NN_MAX * 4];
__device__ float    g_as2 [NN_MAX];
__device__ float    g_ad2 [NN_MAX];
__device__ float    g_logits[NN_MAX];
__device__ unsigned g_maxu[6];
__device__ float    g_sum [1];
// CSR
__device__ int      g_deg   [NN_MAX];
__device__ int      g_rowptr[NN_MAX + 1];
__device__ int      g_cursor[NN_MAX];
__device__ int      g_col   [E_MAX + NN_MAX];
// W transposed hi/lo (fp16), [N=128][K] row-major
__device__ __half   g_W1tH[256 * 128];
__device__ __half   g_W1tL[256 * 128];
__device__ __half   g_W2tH[128 * 128];
__device__ __half   g_W2tL[128 * 128];

// ---------------- helpers ----------------
__device__ __forceinline__ unsigned ford(float f) {
    unsigned u = __float_as_uint(f);
    return (u & 0x80000000u) ? ~u : (u | 0x80000000u);
}
__device__ __forceinline__ float forddec(unsigned u) {
    return (u & 0x80000000u) ? __uint_as_float(u & 0x7fffffffu) : __uint_as_float(~u);
}
__device__ __forceinline__ float lrelu(float v) { return v > 0.f ? v : 0.2f * v; }
__device__ __forceinline__ float elu(float v)   { return v > 0.f ? v : expm1f(v); }

__device__ __forceinline__ uint32_t smem_u32(const void* p) {
    uint32_t a;
    asm("{ .reg .u64 t; cvta.to.shared.u64 t, %1; cvt.u32.u64 %0, t; }" : "=r"(a) : "l"(p));
    return a;
}
__device__ __forceinline__ void ldsm4(uint32_t a, uint32_t* r) {
    asm volatile("ldmatrix.sync.aligned.m8n8.x4.shared.b16 {%0,%1,%2,%3}, [%4];"
        : "=r"(r[0]), "=r"(r[1]), "=r"(r[2]), "=r"(r[3]) : "r"(a));
}
__device__ __forceinline__ void mma16816(float* c, const uint32_t* a, uint32_t b0, uint32_t b1) {
    asm volatile(
        "mma.sync.aligned.m16n8k16.row.col.f32.f16.f16.f32 "
        "{%0,%1,%2,%3}, {%4,%5,%6,%7}, {%8,%9}, {%0,%1,%2,%3};"
        : "+f"(c[0]), "+f"(c[1]), "+f"(c[2]), "+f"(c[3])
        : "r"(a[0]), "r"(a[1]), "r"(a[2]), "r"(a[3]), "r"(b0), "r"(b1));
}
__device__ __forceinline__ void h8(uint4 q, float* f) {
    float2 a = __half22float2(*(__half2*)&q.x);
    float2 b = __half22float2(*(__half2*)&q.y);
    float2 c = __half22float2(*(__half2*)&q.z);
    float2 d = __half22float2(*(__half2*)&q.w);
    f[0] = a.x; f[1] = a.y; f[2] = b.x; f[3] = b.y;
    f[4] = c.x; f[5] = c.y; f[6] = d.x; f[7] = d.y;
}

// ---------------- fused init: W fp16 hi/lo split + zeroing ----------------
__global__ void k_init(const float* __restrict__ W1, int K1, const float* __restrict__ W2,
                       float* __restrict__ pooled, int n, int B_w) {
    int b = blockIdx.x, tid = threadIdx.x;
    if (b < B_w) {
        int idx = b * 256 + tid;
        int n1 = K1 * 128;
        const float* W; __half *H, *L; int K;
        if (idx < n1) { W = W1; H = g_W1tH; L = g_W1tL; K = K1; }
        else { idx -= n1; if (idx >= 128 * 128) return; W = W2; H = g_W2tH; L = g_W2tL; K = 128; }
        int k = idx >> 7, nc = idx & 127;
        float v = W[idx];
        __half h = __float2half(v);
        H[(size_t)nc * K + k] = h;
        L[(size_t)nc * K + k] = __float2half(v - __half2float(h));
        return;
    }
    int gid = (b - B_w) * 256 + tid;
    if (gid < n) g_deg[gid] = 0;
    if (gid < 6) g_maxu[gid] = 0;
    if (gid == 6) g_sum[0] = 0.f;
    if (gid >= 32 && gid < 160) pooled[gid - 32] = 0.f;
}

// ---------------- HMMA GEMM, M-tile 64, 2-term fp16; C fp16, occ 4 ---------
#define SSTR 72
#define SM_A  0                        // 64 * 144 = 9216
#define SM_BH 9216                     // 128 * 144 = 18432
#define SM_BL 27648
#define SM_TOT 46080

template<int MODE>
__global__ void __launch_bounds__(256, 4)
gemm_tc(const float* __restrict__ A, const __half* __restrict__ Ah,
        int M, int K,
        const __half* __restrict__ BtH, const __half* __restrict__ BtL,
        __half* __restrict__ Ch,
        const float* __restrict__ attS, const float* __restrict__ attD,
        float* __restrict__ asOut, float* __restrict__ adOut, int heads) {
    extern __shared__ __align__(128) char smem[];
    uint32_t sb = smem_u32(smem);
    int tid = threadIdx.x, lane = tid & 31, w = tid >> 5;
    int wm = w >> 1, wn = w & 1;           // 4 x 2 warp grid; warp tile 16 x 64
    int row0 = blockIdx.x * 64;
    int lr = lane & 15, lc = lane >> 4;

    float acc[8][4];                        // [nb][4], nb = 8 n8-blocks
#pragma unroll
    for (int i = 0; i < 8; i++)
#pragma unroll
        for (int j = 0; j < 4; j++) acc[i][j] = 0.f;

    for (int k0 = 0; k0 < K; k0 += 64) {
        // ---- fill A (64 rows x 64 cols) ----
        if (MODE == 1) {
#pragma unroll
            for (int i = 0; i < 4; i++) {
                int f = tid + i * 256;
                int r = f >> 4, c4 = (f & 15) << 2;
                float4 a = make_float4(0.f, 0.f, 0.f, 0.f);
                if (row0 + r < M)
                    a = *(const float4*)&A[(size_t)(row0 + r) * K + k0 + c4];
                __half2 p0 = __float22half2_rn(make_float2(a.x, a.y));
                __half2 p1 = __float22half2_rn(make_float2(a.z, a.w));
                uint32_t off = (uint32_t)(r * SSTR + c4) * 2;
                *(uint32_t*)(smem + SM_A + off)     = *(uint32_t*)&p0;
                *(uint32_t*)(smem + SM_A + off + 4) = *(uint32_t*)&p1;
            }
        } else {
#pragma unroll
            for (int i = 0; i < 2; i++) {
                int f = tid + i * 256;
                int r = f >> 3, u = (f & 7) << 3;
                uint4 z = make_uint4(0, 0, 0, 0);
                if (row0 + r < M)
                    z = *(const uint4*)&Ah[(size_t)(row0 + r) * K + k0 + u];
                *(uint4*)(smem + SM_A + (uint32_t)(r * SSTR + u) * 2) = z;
            }
        }
        // ---- fill B hi/lo (128 n-rows x 64 k) ----
#pragma unroll
        for (int i = 0; i < 4; i++) {
            int f = tid + i * 256;
            int r = f >> 3, u = (f & 7) << 3;
            uint32_t off = (uint32_t)(r * SSTR + u) * 2;
            *(uint4*)(smem + SM_BH + off) = *(const uint4*)&BtH[(size_t)r * K + k0 + u];
            *(uint4*)(smem + SM_BL + off) = *(const uint4*)&BtL[(size_t)r * K + k0 + u];
        }
        __syncthreads();

#pragma unroll
        for (int ks = 0; ks < 4; ks++) {
            uint32_t aF[4];
            {
                uint32_t off = (uint32_t)((wm * 16 + lr) * SSTR + ks * 16 + lc * 8) * 2;
                ldsm4(sb + SM_A + off, aF);
            }
#pragma unroll
            for (int nbp = 0; nbp < 4; nbp++) {
                uint32_t offB = (uint32_t)((wn * 64 + nbp * 16 + lr) * SSTR + ks * 16 + lc * 8) * 2;
                uint32_t bh[4], bl[4];
                ldsm4(sb + SM_BH + offB, bh);
                ldsm4(sb + SM_BL + offB, bl);
                float* c0 = acc[nbp * 2];
                float* c1 = acc[nbp * 2 + 1];
                mma16816(c0, aF, bh[0], bh[2]);
                mma16816(c0, aF, bl[0], bl[2]);
                mma16816(c1, aF, bh[1], bh[3]);
                mma16816(c1, aF, bl[1], bl[3]);
            }
        }
        __syncthreads();
    }

    // ---- epilogue: store C (fp16) + fused attention dots + global as-max ----
    float* sred = (float*)smem;               // [64][4]
    unsigned* smax = (unsigned*)(smem + 2048);
    if (tid < 8) smax[tid] = 0u;
    __syncthreads();

    int g = lane >> 2, tq = lane & 3;
    float pS[4], pD[4];                       // [half*2 + sub]
#pragma unroll
    for (int i = 0; i < 4; i++) { pS[i] = 0.f; pD[i] = 0.f; }

#pragma unroll
    for (int nb = 0; nb < 8; nb++) {
        int col = wn * 64 + nb * 8 + tq * 2;
        float* c = acc[nb];
        float s0 = attS[col], s1 = attS[col + 1];
        float d0 = attD[col], d1 = attD[col + 1];
        int sub = nb >> 2;
        pS[sub]     += c[0] * s0 + c[1] * s1;
        pS[2 + sub] += c[2] * s0 + c[3] * s1;
        pD[sub]     += c[0] * d0 + c[1] * d1;
        pD[2 + sub] += c[2] * d0 + c[3] * d1;
        int r = row0 + wm * 16 + g;
        if (r < M) {
            __half2 p = __float22half2_rn(make_float2(c[0], c[1]));
            *(__half2*)&Ch[(size_t)r * 128 + col] = p;
        }
        if (r + 8 < M) {
            __half2 p = __float22half2_rn(make_float2(c[2], c[3]));
            *(__half2*)&Ch[(size_t)(r + 8) * 128 + col] = p;
        }
    }
#pragma unroll
    for (int o = 1; o <= 2; o <<= 1) {
#pragma unroll
        for (int i = 0; i < 4; i++) {
            pS[i] += __shfl_xor_sync(0xffffffffu, pS[i], o);
            pD[i] += __shfl_xor_sync(0xffffffffu, pD[i], o);
        }
    }
    if (tq == 0) {
#pragma unroll
        for (int half = 0; half < 2; half++) {
            int rl = wm * 16 + half * 8 + g;
            int r = row0 + rl;
            int i0 = half * 2;
            if (heads == 4) {
                if (r < M) {
                    asOut[r * 4 + wn * 2 + 0] = pS[i0 + 0];
                    asOut[r * 4 + wn * 2 + 1] = pS[i0 + 1];
                    adOut[r * 4 + wn * 2 + 0] = pD[i0 + 0];
                    adOut[r * 4 + wn * 2 + 1] = pD[i0 + 1];
                    atomicMax(&smax[wn * 2 + 0], ford(pS[i0 + 0]));
                    atomicMax(&smax[wn * 2 + 1], ford(pS[i0 + 1]));
                }
            } else {
                sred[rl * 4 + wn * 2 + 0] = pS[i0] + pS[i0 + 1];
                sred[rl * 4 + wn * 2 + 1] = pD[i0] + pD[i0 + 1];
            }
        }
    }
    __syncthreads();
    if (heads == 4) {
        if (tid < 4) atomicMax(&g_maxu[tid], smax[tid]);
    } else {
        if (tid < 64) {
            int r = row0 + tid;
            if (r < M) {
                float S = sred[tid * 4 + 0] + sred[tid * 4 + 2];
                float D = sred[tid * 4 + 1] + sred[tid * 4 + 3];
                asOut[r] = S;
                adOut[r] = D;
                atomicMax(&smax[0], ford(S));
            }
        }
        __syncthreads();
        if (tid == 0) atomicMax(&g_maxu[4], smax[0]);
    }
}

// ---------------- CSR build ----------------
__global__ void k_hist(const int* __restrict__ dst, int E, int n) {
    int e = blockIdx.x * blockDim.x + threadIdx.x;
    if (e >= E + n) return;
    int d = (e < E) ? dst[e] : (e - E);
    atomicAdd(&g_deg[d], 1);
}

__global__ void k_prefix(int n) {
    __shared__ int sh[1024];
    int t = threadIdx.x;
    int chunk = (n + 1023) / 1024;
    int lo = t * chunk, hi = min(lo + chunk, n);
    int part = 0;
    for (int i = lo; i < hi; i++) part += g_deg[i];
    sh[t] = part;
    __syncthreads();
    for (int off = 1; off < 1024; off <<= 1) {
        int v = (t >= off) ? sh[t - off] : 0;
        __syncthreads();
        sh[t] += v;
        __syncthreads();
    }
    int base = (t == 0) ? 0 : sh[t - 1];
    for (int i = lo; i < hi; i++) {
        g_rowptr[i] = base;
        g_cursor[i] = base;
        base += g_deg[i];
    }
    if (t == 0) g_rowptr[n] = sh[1023];
}

__global__ void k_scatter(const int* __restrict__ src, const int* __restrict__ dst, int E, int n) {
    int e = blockIdx.x * blockDim.x + threadIdx.x;
    if (e >= E + n) return;
    int s, d;
    if (e < E) { s = src[e]; d = dst[e]; } else { s = e - E; d = s; }
    int pos = atomicAdd(&g_cursor[d], 1);
    g_col[pos] = s;
}

// ---------------- layer-1 gather: 2 edges/warp (16 lanes each) -------------
__global__ void gather1(const float* __restrict__ b1, int n) {
    int d = (blockIdx.x * blockDim.x + threadIdx.x) >> 5;
    int lane = threadIdx.x & 31;
    if (d >= n) return;
    int grp = lane >> 4, l = lane & 15;
    int h = l >> 2;
    int r0 = g_rowptr[d], r1 = g_rowptr[d + 1];
    float ad_h = g_ad1[d * 4 + h];
    float m_h = lrelu(forddec(g_maxu[h]) + ad_h);

    float acc[8];
#pragma unroll
    for (int j = 0; j < 8; j++) acc[j] = 0.f;
    float den = 0.f;

    int e = r0 + grp;
    for (; e + 2 < r1; e += 4) {
        int s0 = g_col[e], s1 = g_col[e + 2];
        float a0 = g_as1[s0 * 4 + h], a1 = g_as1[s1 * 4 + h];
        uint4 q0 = *(const uint4*)&g_xwh[(size_t)s0 * 128 + l * 8];
        uint4 q1 = *(const uint4*)&g_xwh[(size_t)s1 * 128 + l * 8];
        float w0 = __expf(lrelu(a0 + ad_h) - m_h);
        float w1 = __expf(lrelu(a1 + ad_h) - m_h);
        float x0[8], x1[8];
        h8(q0, x0); h8(q1, x1);
        den += w0 + w1;
#pragma unroll
        for (int j = 0; j < 8; j++) acc[j] += w0 * x0[j] + w1 * x1[j];
    }
    if (e < r1) {
        int s0 = g_col[e];
        float w0 = __expf(lrelu(g_as1[s0 * 4 + h] + ad_h) - m_h);
        uint4 q0 = *(const uint4*)&g_xwh[(size_t)s0 * 128 + l * 8];
        float x0[8];
        h8(q0, x0);
        den += w0;
#pragma unroll
        for (int j = 0; j < 8; j++) acc[j] += w0 * x0[j];
    }
#pragma unroll
    for (int j = 0; j < 8; j++) acc[j] += __shfl_xor_sync(0xffffffffu, acc[j], 16);
    den += __shfl_xor_sync(0xffffffffu, den, 16);

    if (grp == 0) {
        float inv = 1.f / (den + 1e-16f);
        __half hv[8];
#pragma unroll
        for (int j = 0; j < 8; j++)
            hv[j] = __float2half(elu(acc[j] * inv + b1[l * 8 + j]));
        *(uint4*)&g_x2[(size_t)d * 128 + l * 8] = *(uint4*)hv;
    }
}

// ---------------- layer-2 gather: 2 edges/warp, fused ents+logits ----------
__global__ void gather2(const float* __restrict__ b2, const float* __restrict__ Wq,
                        const int* __restrict__ qmask, float* __restrict__ ents, int n) {
    int d = (blockIdx.x * blockDim.x + threadIdx.x) >> 5;
    int lane = threadIdx.x & 31;
    if (d >= n) return;
    int grp = lane >> 4, l = lane & 15;
    int r0 = g_rowptr[d], r1 = g_rowptr[d + 1];
    float ad = g_ad2[d];
    float mx = lrelu(forddec(g_maxu[4]) + ad);

    float acc[8];
#pragma unroll
    for (int j = 0; j < 8; j++) acc[j] = 0.f;
    float den = 0.f;

    int e = r0 + grp;
    for (; e + 2 < r1; e += 4) {
        int s0 = g_col[e], s1 = g_col[e + 2];
        float a0 = g_as2[s0], a1 = g_as2[s1];
        uint4 q0 = *(const uint4*)&g_xwh[(size_t)s0 * 128 + l * 8];
        uint4 q1 = *(const uint4*)&g_xwh[(size_t)s1 * 128 + l * 8];
        float w0 = __expf(lrelu(a0 + ad) - mx);
        float w1 = __expf(lrelu(a1 + ad) - mx);
        float x0[8], x1[8];
        h8(q0, x0); h8(q1, x1);
        den += w0 + w1;
#pragma unroll
        for (int j = 0; j < 8; j++) acc[j] += w0 * x0[j] + w1 * x1[j];
    }
    if (e < r1) {
        int s0 = g_col[e];
        float w0 = __expf(lrelu(g_as2[s0] + ad) - mx);
        uint4 q0 = *(const uint4*)&g_xwh[(size_t)s0 * 128 + l * 8];
        float x0[8];
        h8(q0, x0);
        den += w0;
#pragma unroll
        for (int j = 0; j < 8; j++) acc[j] += w0 * x0[j];
    }
#pragma unroll
    for (int j = 0; j < 8; j++) acc[j] += __shfl_xor_sync(0xffffffffu, acc[j], 16);
    den += __shfl_xor_sync(0xffffffffu, den, 16);

    float inv = 1.f / (den + 1e-16f);
    float v[8];
    float dotp = 0.f;
#pragma unroll
    for (int j = 0; j < 8; j++) {
        v[j] = elu(acc[j] * inv + b2[l * 8 + j]);
        dotp += v[j] * Wq[l * 8 + j];
    }
    if (grp == 0) {
        float4 o0 = make_float4(v[0], v[1], v[2], v[3]);
        float4 o1 = make_float4(v[4], v[5], v[6], v[7]);
        *(float4*)&ents[(size_t)d * 128 + l * 8]     = o0;
        *(float4*)&ents[(size_t)d * 128 + l * 8 + 4] = o1;
    }
#pragma unroll
    for (int o = 8; o; o >>= 1) dotp += __shfl_xor_sync(0xffffffffu, dotp, o);
    if (lane == 0) {
        float logit = dotp + ((float)qmask[d] - 1.f) * 1e9f;
        g_logits[d] = logit;
        atomicMax(&g_maxu[5], ford(logit));
    }
}

// ---------------- fused expsum + pooled accumulation ----------------
__global__ void k_expsum_pool(const float* __restrict__ ents, float* __restrict__ attn,
                              float* __restrict__ pooled, int n) {
    int t = threadIdx.x;
    float M = forddec(g_maxu[5]);
    float acc = 0.f, se = 0.f;
    for (int nn = blockIdx.x; nn < n; nn += gridDim.x) {
        float e = __expf(g_logits[nn] - M);
        if (t == 0) attn[nn] = e;
        se += e;
        acc += e * ents[(size_t)nn * 128 + t];
    }
    atomicAdd(&pooled[t], acc);
    if (t == 0) atomicAdd(&g_sum[0], se);
}

__global__ void k_norm(float* __restrict__ attn, float* __restrict__ pooled, int n) {
    float inv = 1.f / g_sum[0];
    for (int i = blockIdx.x * blockDim.x + threadIdx.x; i < n; i += gridDim.x * blockDim.x) {
        attn[i] *= inv;
        if (i < 128) pooled[i] *= inv;
    }
}

// ---------------- launch ----------------
extern "C" void kernel_launch(void* const* d_in, const int* in_sizes, int n_in,
                              void* d_out, int out_size) {
    const float* x     = (const float*)d_in[0];
    const int*   eidx  = (const int*)  d_in[1];
    const int*   qmask = (const int*)  d_in[3];
    const float* W1    = (const float*)d_in[5];
    const float* as1w  = (const float*)d_in[6];
    const float* ad1w  = (const float*)d_in[7];
    const float* b1    = (const float*)d_in[8];
    const float* W2    = (const float*)d_in[9];
    const float* as2w  = (const float*)d_in[10];
    const float* ad2w  = (const float*)d_in[11];
    const float* b2    = (const float*)d_in[12];
    const float* Wq    = (const float*)d_in[13];

    const int n = in_sizes[3];
    const int E = in_sizes[1] / 2;
    const int K1 = in_sizes[0] / n;
    const int ET = E + n;

    const int* src = eidx;
    const int* dst = eidx + E;

    float* out    = (float*)d_out;
    float* pooled = out;
    float* ents   = out + 128;
    float* attn   = out + 128 + (size_t)n * 128;

    float *g_as1_p, *g_ad1_p, *g_as2_p, *g_ad2_p;
    cudaGetSymbolAddress((void**)&g_as1_p, g_as1);
    cudaGetSymbolAddress((void**)&g_ad1_p, g_ad1);
    cudaGetSymbolAddress((void**)&g_as2_p, g_as2);
    cudaGetSymbolAddress((void**)&g_ad2_p, g_ad2);
    __half *w1h, *w1l, *w2h, *w2l, *x2p, *xwh;
    cudaGetSymbolAddress((void**)&w1h, g_W1tH);
    cudaGetSymbolAddress((void**)&w1l, g_W1tL);
    cudaGetSymbolAddress((void**)&w2h, g_W2tH);
    cudaGetSymbolAddress((void**)&w2l, g_W2tL);
    cudaGetSymbolAddress((void**)&x2p, g_x2);
    cudaGetSymbolAddress((void**)&xwh, g_xwh);

    cudaFuncSetAttribute(gemm_tc<1>, cudaFuncAttributeMaxDynamicSharedMemorySize, SM_TOT);
    cudaFuncSetAttribute(gemm_tc<0>, cudaFuncAttributeMaxDynamicSharedMemorySize, SM_TOT);

    const int gblk = (n + 63) / 64;
    const int B_w  = ((K1 + 128) * 128 + 255) / 256;
    const int B_z  = (n + 255) / 256;

    cudaStream_t sB = cudaStreamPerThread;
    cudaEvent_t evF, evJ;
    cudaEventCreateWithFlags(&evF, cudaEventDisableTiming);
    cudaEventCreateWithFlags(&evJ, cudaEventDisableTiming);

    k_init<<<B_w + B_z, 256>>>(W1, K1, W2, pooled, n, B_w);
    cudaEventRecord(evF, 0);
    cudaStreamWaitEvent(sB, evF, 0);

    k_hist<<<(ET + 255) / 256, 256, 0, sB>>>(dst, E, n);
    k_prefix<<<1, 1024, 0, sB>>>(n);

    gemm_tc<1><<<gblk, 256, SM_TOT>>>(x, nullptr, n, K1, w1h, w1l, xwh,
                                      as1w, ad1w, g_as1_p, g_ad1_p, 4);

    k_scatter<<<(ET + 255) / 256, 256, 0, sB>>>(src, dst, E, n);
    cudaEventRecord(evJ, sB);
    cudaStreamWaitEvent(0, evJ, 0);

    gather1<<<(n + 7) / 8, 256>>>(b1, n);
    gemm_tc<0><<<gblk, 256, SM_TOT>>>(nullptr, x2p, n, 128, w2h, w2l, xwh,
                                      as2w, ad2w, g_as2_p, g_ad2_p, 1);
    gather2<<<(n + 7) / 8, 256>>>(b2, Wq, qmask, ents, n);
    k_expsum_pool<<<512, 128>>>(ents, attn, pooled, n);
    k_norm<<<(n + 255) / 256, 256>>>(attn, pooled, n);

    cudaEventDestroy(evF);
    cudaEventDestroy(evJ);
}

// round 15
// speedup vs baseline: 1.0469x; 1.0469x over previous
#include <cuda_runtime.h>
#include <cuda_bf16.h>
#include <cuda_fp16.h>
#include <math.h>
#include <stdint.h>

#define NN_MAX 50000
#define E_MAX  800000
#define CSR_NB 296

// ---------------- scratch (device globals; no allocation) ----------------
__device__ __half   g_xwh[NN_MAX * 128];
__device__ __half   g_x2 [NN_MAX * 128];
__device__ float    g_as1 [NN_MAX * 4];
__device__ float    g_ad1 [NN_MAX * 4];
__device__ float    g_as2 [NN_MAX];
__device__ float    g_ad2 [NN_MAX];
__device__ float    g_logits[NN_MAX];
__device__ unsigned g_maxu[6];
__device__ float    g_sum [1];
__device__ int      g_cnt [1];
__device__ int      g_flag[1];
// CSR
__device__ int      g_deg   [NN_MAX];
__device__ int      g_rowptr[NN_MAX + 1];
__device__ int      g_cursor[NN_MAX];
__device__ int      g_col   [E_MAX + NN_MAX];
// W transposed hi/lo (fp16), [N=128][K] row-major
__device__ __half   g_W1tH[256 * 128];
__device__ __half   g_W1tL[256 * 128];
__device__ __half   g_W2tH[128 * 128];
__device__ __half   g_W2tL[128 * 128];

// ---------------- helpers ----------------
__device__ __forceinline__ unsigned ford(float f) {
    unsigned u = __float_as_uint(f);
    return (u & 0x80000000u) ? ~u : (u | 0x80000000u);
}
__device__ __forceinline__ float forddec(unsigned u) {
    return (u & 0x80000000u) ? __uint_as_float(u & 0x7fffffffu) : __uint_as_float(~u);
}
__device__ __forceinline__ float lrelu(float v) { return v > 0.f ? v : 0.2f * v; }
__device__ __forceinline__ float elu(float v)   { return v > 0.f ? v : expm1f(v); }

__device__ __forceinline__ uint32_t smem_u32(const void* p) {
    uint32_t a;
    asm("{ .reg .u64 t; cvta.to.shared.u64 t, %1; cvt.u32.u64 %0, t; }" : "=r"(a) : "l"(p));
    return a;
}
__device__ __forceinline__ void ldsm4(uint32_t a, uint32_t* r) {
    asm volatile("ldmatrix.sync.aligned.m8n8.x4.shared.b16 {%0,%1,%2,%3}, [%4];"
        : "=r"(r[0]), "=r"(r[1]), "=r"(r[2]), "=r"(r[3]) : "r"(a));
}
__device__ __forceinline__ void mma16816(float* c, const uint32_t* a, uint32_t b0, uint32_t b1) {
    asm volatile(
        "mma.sync.aligned.m16n8k16.row.col.f32.f16.f16.f32 "
        "{%0,%1,%2,%3}, {%4,%5,%6,%7}, {%8,%9}, {%0,%1,%2,%3};"
        : "+f"(c[0]), "+f"(c[1]), "+f"(c[2]), "+f"(c[3])
        : "r"(a[0]), "r"(a[1]), "r"(a[2]), "r"(a[3]), "r"(b0), "r"(b1));
}
__device__ __forceinline__ void h8(uint4 q, float* f) {
    float2 a = __half22float2(*(__half2*)&q.x);
    float2 b = __half22float2(*(__half2*)&q.y);
    float2 c = __half22float2(*(__half2*)&q.z);
    float2 d = __half22float2(*(__half2*)&q.w);
    f[0] = a.x; f[1] = a.y; f[2] = b.x; f[3] = b.y;
    f[4] = c.x; f[5] = c.y; f[6] = d.x; f[7] = d.y;
}

// ---------------- fused init: W fp16 hi/lo split + zeroing ----------------
__global__ void k_init(const float* __restrict__ W1, int K1, const float* __restrict__ W2,
                       float* __restrict__ pooled, int n, int B_w) {
    int b = blockIdx.x, tid = threadIdx.x;
    if (b < B_w) {
        int idx = b * 256 + tid;
        int n1 = K1 * 128;
        const float* W; __half *H, *L; int K;
        if (idx < n1) { W = W1; H = g_W1tH; L = g_W1tL; K = K1; }
        else { idx -= n1; if (idx >= 128 * 128) return; W = W2; H = g_W2tH; L = g_W2tL; K = 128; }
        int k = idx >> 7, nc = idx & 127;
        float v = W[idx];
        __half h = __float2half(v);
        H[(size_t)nc * K + k] = h;
        L[(size_t)nc * K + k] = __float2half(v - __half2float(h));
        return;
    }
    int gid = (b - B_w) * 256 + tid;
    if (gid < n) g_deg[gid] = 0;
    if (gid < 6) g_maxu[gid] = 0;
    if (gid == 6) g_sum[0] = 0.f;
    if (gid == 7) g_cnt[0] = 0;
    if (gid == 8) g_flag[0] = 0;
    if (gid >= 32 && gid < 160) pooled[gid - 32] = 0.f;
}

// ---------------- persistent CSR: hist -> prefix -> scatter (one kernel) ----
__global__ void __launch_bounds__(256, 8)
k_csr(const int* __restrict__ src, const int* __restrict__ dst, int E, int n) {
    int tid = threadIdx.x;
    int gid0 = blockIdx.x * 256 + tid;
    int gstride = CSR_NB * 256;
    int ET = E + n;

    // phase 1: histogram (grid-stride)
    for (int e = gid0; e < ET; e += gstride) {
        int d = (e < E) ? dst[e] : (e - E);
        atomicAdd(&g_deg[d], 1);
    }
    __syncthreads();
    __threadfence();

    if (blockIdx.x == 0) {
        // wait for all other blocks to finish hist
        if (tid == 0) {
            while (atomicAdd(&g_cnt[0], 0) < CSR_NB - 1) __nanosleep(100);
        }
        __syncthreads();
        // prefix scan (256 threads over n)
        __shared__ int sh[256];
        int chunk = (n + 255) / 256;
        int lo = tid * chunk, hi = min(lo + chunk, n);
        int part = 0;
        for (int i = lo; i < hi; i++) part += g_deg[i];
        sh[tid] = part;
        __syncthreads();
        for (int off = 1; off < 256; off <<= 1) {
            int v = (tid >= off) ? sh[tid - off] : 0;
            __syncthreads();
            sh[tid] += v;
            __syncthreads();
        }
        int base = (tid == 0) ? 0 : sh[tid - 1];
        for (int i = lo; i < hi; i++) {
            g_rowptr[i] = base;
            g_cursor[i] = base;
            base += g_deg[i];
        }
        if (tid == 0) g_rowptr[n] = sh[255];
        __threadfence();
        __syncthreads();
        if (tid == 0) atomicExch(&g_flag[0], 1);
    } else {
        if (tid == 0) {
            atomicAdd(&g_cnt[0], 1);
            while (atomicAdd(&g_flag[0], 0) == 0) __nanosleep(100);
        }
        __syncthreads();
    }

    // phase 3: scatter (grid-stride)
    for (int e = gid0; e < ET; e += gstride) {
        int s, d;
        if (e < E) { s = src[e]; d = dst[e]; } else { s = e - E; d = s; }
        int pos = atomicAdd(&g_cursor[d], 1);
        g_col[pos] = s;
    }
}

// ---------------- HMMA GEMM (R13): M128, 2-term fp16, occ 2; C fp16 --------
#define SSTR 72
#define SM_A  0
#define SM_BH 18432
#define SM_BL 36864
#define SM_TOT 55296

template<int MODE>
__global__ void __launch_bounds__(256, 2)
gemm_tc(const float* __restrict__ A, const __half* __restrict__ Ah,
        int M, int K,
        const __half* __restrict__ BtH, const __half* __restrict__ BtL,
        __half* __restrict__ Ch,
        const float* __restrict__ attS, const float* __restrict__ attD,
        float* __restrict__ asOut, float* __restrict__ adOut, int heads) {
    extern __shared__ __align__(128) char smem[];
    uint32_t sb = smem_u32(smem);
    int tid = threadIdx.x, lane = tid & 31, w = tid >> 5;
    int wm = w >> 1, wn = w & 1;
    int row0 = blockIdx.x * 128;
    int lr = lane & 15, lc = lane >> 4;

    float acc[16][4];
#pragma unroll
    for (int i = 0; i < 16; i++)
#pragma unroll
        for (int j = 0; j < 4; j++) acc[i][j] = 0.f;

    for (int k0 = 0; k0 < K; k0 += 64) {
        if (MODE == 1) {
#pragma unroll
            for (int i = 0; i < 8; i++) {
                int f = tid + i * 256;
                int r = f >> 4, c4 = (f & 15) << 2;
                float4 a = make_float4(0.f, 0.f, 0.f, 0.f);
                if (row0 + r < M)
                    a = *(const float4*)&A[(size_t)(row0 + r) * K + k0 + c4];
                __half2 p0 = __float22half2_rn(make_float2(a.x, a.y));
                __half2 p1 = __float22half2_rn(make_float2(a.z, a.w));
                uint32_t off = (uint32_t)(r * SSTR + c4) * 2;
                *(uint32_t*)(smem + SM_A + off)     = *(uint32_t*)&p0;
                *(uint32_t*)(smem + SM_A + off + 4) = *(uint32_t*)&p1;
            }
        } else {
#pragma unroll
            for (int i = 0; i < 4; i++) {
                int f = tid + i * 256;
                int r = f >> 3, u = (f & 7) << 3;
                uint4 z = make_uint4(0, 0, 0, 0);
                if (row0 + r < M)
                    z = *(const uint4*)&Ah[(size_t)(row0 + r) * K + k0 + u];
                *(uint4*)(smem + SM_A + (uint32_t)(r * SSTR + u) * 2) = z;
            }
        }
#pragma unroll
        for (int i = 0; i < 4; i++) {
            int f = tid + i * 256;
            int r = f >> 3, u = (f & 7) << 3;
            uint32_t off = (uint32_t)(r * SSTR + u) * 2;
            *(uint4*)(smem + SM_BH + off) = *(const uint4*)&BtH[(size_t)r * K + k0 + u];
            *(uint4*)(smem + SM_BL + off) = *(const uint4*)&BtL[(size_t)r * K + k0 + u];
        }
        __syncthreads();

#pragma unroll
        for (int ks = 0; ks < 4; ks++) {
            uint32_t aF[2][4];
#pragma unroll
            for (int mb = 0; mb < 2; mb++) {
                uint32_t off = (uint32_t)((wm * 32 + mb * 16 + lr) * SSTR + ks * 16 + lc * 8) * 2;
                ldsm4(sb + SM_A + off, aF[mb]);
            }
#pragma unroll
            for (int nbp = 0; nbp < 4; nbp++) {
                uint32_t offB = (uint32_t)((wn * 64 + nbp * 16 + lr) * SSTR + ks * 16 + lc * 8) * 2;
                uint32_t bh[4], bl[4];
                ldsm4(sb + SM_BH + offB, bh);
                ldsm4(sb + SM_BL + offB, bl);
#pragma unroll
                for (int mb = 0; mb < 2; mb++) {
                    float* c0 = acc[mb * 8 + nbp * 2];
                    float* c1 = acc[mb * 8 + nbp * 2 + 1];
                    mma16816(c0, aF[mb], bh[0], bh[2]);
                    mma16816(c0, aF[mb], bl[0], bl[2]);
                    mma16816(c1, aF[mb], bh[1], bh[3]);
                    mma16816(c1, aF[mb], bl[1], bl[3]);
                }
            }
        }
        __syncthreads();
    }

    // ---- epilogue ----
    float* sred = (float*)smem;
    unsigned* smax = (unsigned*)(smem + 2048);
    if (tid < 8) smax[tid] = 0u;
    __syncthreads();

    int g = lane >> 2, tq = lane & 3;
    float pS[8], pD[8];
#pragma unroll
    for (int i = 0; i < 8; i++) { pS[i] = 0.f; pD[i] = 0.f; }

#pragma unroll
    for (int mb = 0; mb < 2; mb++) {
#pragma unroll
        for (int nb = 0; nb < 8; nb++) {
            int col = wn * 64 + nb * 8 + tq * 2;
            float* c = acc[mb * 8 + nb];
            float s0 = attS[col], s1 = attS[col + 1];
            float d0 = attD[col], d1 = attD[col + 1];
            int sub = nb >> 2;
            pS[mb * 4 + sub]     += c[0] * s0 + c[1] * s1;
            pS[mb * 4 + 2 + sub] += c[2] * s0 + c[3] * s1;
            pD[mb * 4 + sub]     += c[0] * d0 + c[1] * d1;
            pD[mb * 4 + 2 + sub] += c[2] * d0 + c[3] * d1;
            int r = row0 + wm * 32 + mb * 16 + g;
            if (r < M) {
                __half2 p = __float22half2_rn(make_float2(c[0], c[1]));
                *(__half2*)&Ch[(size_t)r * 128 + col] = p;
            }
            if (r + 8 < M) {
                __half2 p = __float22half2_rn(make_float2(c[2], c[3]));
                *(__half2*)&Ch[(size_t)(r + 8) * 128 + col] = p;
            }
        }
    }
#pragma unroll
    for (int o = 1; o <= 2; o <<= 1) {
#pragma unroll
        for (int i = 0; i < 8; i++) {
            pS[i] += __shfl_xor_sync(0xffffffffu, pS[i], o);
            pD[i] += __shfl_xor_sync(0xffffffffu, pD[i], o);
        }
    }
    if (tq == 0) {
#pragma unroll
        for (int mb = 0; mb < 2; mb++) {
#pragma unroll
            for (int half = 0; half < 2; half++) {
                int rl = wm * 32 + mb * 16 + half * 8 + g;
                int r = row0 + rl;
                int i0 = mb * 4 + half * 2;
                if (heads == 4) {
                    if (r < M) {
                        asOut[r * 4 + wn * 2 + 0] = pS[i0 + 0];
                        asOut[r * 4 + wn * 2 + 1] = pS[i0 + 1];
                        adOut[r * 4 + wn * 2 + 0] = pD[i0 + 0];
                        adOut[r * 4 + wn * 2 + 1] = pD[i0 + 1];
                        atomicMax(&smax[wn * 2 + 0], ford(pS[i0 + 0]));
                        atomicMax(&smax[wn * 2 + 1], ford(pS[i0 + 1]));
                    }
                } else {
                    sred[rl * 4 + wn * 2 + 0] = pS[i0] + pS[i0 + 1];
                    sred[rl * 4 + wn * 2 + 1] = pD[i0] + pD[i0 + 1];
                }
            }
        }
    }
    __syncthreads();
    if (heads == 4) {
        if (tid < 4) atomicMax(&g_maxu[tid], smax[tid]);
    } else {
        if (tid < 128) {
            int r = row0 + tid;
            if (r < M) {
                float S = sred[tid * 4 + 0] + sred[tid * 4 + 2];
                float D = sred[tid * 4 + 1] + sred[tid * 4 + 3];
                asOut[r] = S;
                adOut[r] = D;
                atomicMax(&smax[0], ford(S));
            }
        }
        __syncthreads();
        if (tid == 0) atomicMax(&g_maxu[4], smax[0]);
    }
}

// ---------------- layer-1 gather: 2 edges/warp (16 lanes each) -------------
__global__ void gather1(const float* __restrict__ b1, int n) {
    int d = (blockIdx.x * blockDim.x + threadIdx.x) >> 5;
    int lane = threadIdx.x & 31;
    if (d >= n) return;
    int grp = lane >> 4, l = lane & 15;
    int h = l >> 2;
    int r0 = g_rowptr[d], r1 = g_rowptr[d + 1];
    float ad_h = g_ad1[d * 4 + h];
    float m_h = lrelu(forddec(g_maxu[h]) + ad_h);

    float acc[8];
#pragma unroll
    for (int j = 0; j < 8; j++) acc[j] = 0.f;
    float den = 0.f;

    int e = r0 + grp;
    for (; e + 2 < r1; e += 4) {
        int s0 = g_col[e], s1 = g_col[e + 2];
        float a0 = g_as1[s0 * 4 + h], a1 = g_as1[s1 * 4 + h];
        uint4 q0 = *(const uint4*)&g_xwh[(size_t)s0 * 128 + l * 8];
        uint4 q1 = *(const uint4*)&g_xwh[(size_t)s1 * 128 + l * 8];
        float w0 = __expf(lrelu(a0 + ad_h) - m_h);
        float w1 = __expf(lrelu(a1 + ad_h) - m_h);
        float x0[8], x1[8];
        h8(q0, x0); h8(q1, x1);
        den += w0 + w1;
#pragma unroll
        for (int j = 0; j < 8; j++) acc[j] += w0 * x0[j] + w1 * x1[j];
    }
    if (e < r1) {
        int s0 = g_col[e];
        float w0 = __expf(lrelu(g_as1[s0 * 4 + h] + ad_h) - m_h);
        uint4 q0 = *(const uint4*)&g_xwh[(size_t)s0 * 128 + l * 8];
        float x0[8];
        h8(q0, x0);
        den += w0;
#pragma unroll
        for (int j = 0; j < 8; j++) acc[j] += w0 * x0[j];
    }
#pragma unroll
    for (int j = 0; j < 8; j++) acc[j] += __shfl_xor_sync(0xffffffffu, acc[j], 16);
    den += __shfl_xor_sync(0xffffffffu, den, 16);

    if (grp == 0) {
        float inv = 1.f / (den + 1e-16f);
        __half hv[8];
#pragma unroll
        for (int j = 0; j < 8; j++)
            hv[j] = __float2half(elu(acc[j] * inv + b1[l * 8 + j]));
        *(uint4*)&g_x2[(size_t)d * 128 + l * 8] = *(uint4*)hv;
    }
}

// ---------------- layer-2 gather: 2 edges/warp, fused ents+logits ----------
__global__ void gather2(const float* __restrict__ b2, const float* __restrict__ Wq,
                        const int* __restrict__ qmask, float* __restrict__ ents, int n) {
    int d = (blockIdx.x * blockDim.x + threadIdx.x) >> 5;
    int lane = threadIdx.x & 31;
    if (d >= n) return;
    int grp = lane >> 4, l = lane & 15;
    int r0 = g_rowptr[d], r1 = g_rowptr[d + 1];
    float ad = g_ad2[d];
    float mx = lrelu(forddec(g_maxu[4]) + ad);

    float acc[8];
#pragma unroll
    for (int j = 0; j < 8; j++) acc[j] = 0.f;
    float den = 0.f;

    int e = r0 + grp;
    for (; e + 2 < r1; e += 4) {
        int s0 = g_col[e], s1 = g_col[e + 2];
        float a0 = g_as2[s0], a1 = g_as2[s1];
        uint4 q0 = *(const uint4*)&g_xwh[(size_t)s0 * 128 + l * 8];
        uint4 q1 = *(const uint4*)&g_xwh[(size_t)s1 * 128 + l * 8];
        float w0 = __expf(lrelu(a0 + ad) - mx);
        float w1 = __expf(lrelu(a1 + ad) - mx);
        float x0[8], x1[8];
        h8(q0, x0); h8(q1, x1);
        den += w0 + w1;
#pragma unroll
        for (int j = 0; j < 8; j++) acc[j] += w0 * x0[j] + w1 * x1[j];
    }
    if (e < r1) {
        int s0 = g_col[e];
        float w0 = __expf(lrelu(g_as2[s0] + ad) - mx);
        uint4 q0 = *(const uint4*)&g_xwh[(size_t)s0 * 128 + l * 8];
        float x0[8];
        h8(q0, x0);
        den += w0;
#pragma unroll
        for (int j = 0; j < 8; j++) acc[j] += w0 * x0[j];
    }
#pragma unroll
    for (int j = 0; j < 8; j++) acc[j] += __shfl_xor_sync(0xffffffffu, acc[j], 16);
    den += __shfl_xor_sync(0xffffffffu, den, 16);

    float inv = 1.f / (den + 1e-16f);
    float v[8];
    float dotp = 0.f;
#pragma unroll
    for (int j = 0; j < 8; j++) {
        v[j] = elu(acc[j] * inv + b2[l * 8 + j]);
        dotp += v[j] * Wq[l * 8 + j];
    }
    if (grp == 0) {
        float4 o0 = make_float4(v[0], v[1], v[2], v[3]);
        float4 o1 = make_float4(v[4], v[5], v[6], v[7]);
        *(float4*)&ents[(size_t)d * 128 + l * 8]     = o0;
        *(float4*)&ents[(size_t)d * 128 + l * 8 + 4] = o1;
    }
#pragma unroll
    for (int o = 8; o; o >>= 1) dotp += __shfl_xor_sync(0xffffffffu, dotp, o);
    if (lane == 0) {
        float logit = dotp + ((float)qmask[d] - 1.f) * 1e9f;
        g_logits[d] = logit;
        atomicMax(&g_maxu[5], ford(logit));
    }
}

// ---------------- fused expsum + pooled accumulation ----------------
__global__ void k_expsum_pool(const float* __restrict__ ents, float* __restrict__ attn,
                              float* __restrict__ pooled, int n) {
    int t = threadIdx.x;
    float M = forddec(g_maxu[5]);
    float acc = 0.f, se = 0.f;
    for (int nn = blockIdx.x; nn < n; nn += gridDim.x) {
        float e = __expf(g_logits[nn] - M);
        if (t == 0) attn[nn] = e;
        se += e;
        acc += e * ents[(size_t)nn * 128 + t];
    }
    atomicAdd(&pooled[t], acc);
    if (t == 0) atomicAdd(&g_sum[0], se);
}

__global__ void k_norm(float* __restrict__ attn, float* __restrict__ pooled, int n) {
    float inv = 1.f / g_sum[0];
    for (int i = blockIdx.x * blockDim.x + threadIdx.x; i < n; i += gridDim.x * blockDim.x) {
        attn[i] *= inv;
        if (i < 128) pooled[i] *= inv;
    }
}

// ---------------- launch ----------------
extern "C" void kernel_launch(void* const* d_in, const int* in_sizes, int n_in,
                              void* d_out, int out_size) {
    const float* x     = (const float*)d_in[0];
    const int*   eidx  = (const int*)  d_in[1];
    const int*   qmask = (const int*)  d_in[3];
    const float* W1    = (const float*)d_in[5];
    const float* as1w  = (const float*)d_in[6];
    const float* ad1w  = (const float*)d_in[7];
    const float* b1    = (const float*)d_in[8];
    const float* W2    = (const float*)d_in[9];
    const float* as2w  = (const float*)d_in[10];
    const float* ad2w  = (const float*)d_in[11];
    const float* b2    = (const float*)d_in[12];
    const float* Wq    = (const float*)d_in[13];

    const int n = in_sizes[3];
    const int E = in_sizes[1] / 2;
    const int K1 = in_sizes[0] / n;

    const int* src = eidx;
    const int* dst = eidx + E;

    float* out    = (float*)d_out;
    float* pooled = out;
    float* ents   = out + 128;
    float* attn   = out + 128 + (size_t)n * 128;

    float *g_as1_p, *g_ad1_p, *g_as2_p, *g_ad2_p;
    cudaGetSymbolAddress((void**)&g_as1_p, g_as1);
    cudaGetSymbolAddress((void**)&g_ad1_p, g_ad1);
    cudaGetSymbolAddress((void**)&g_as2_p, g_as2);
    cudaGetSymbolAddress((void**)&g_ad2_p, g_ad2);
    __half *w1h, *w1l, *w2h, *w2l, *x2p, *xwh;
    cudaGetSymbolAddress((void**)&w1h, g_W1tH);
    cudaGetSymbolAddress((void**)&w1l, g_W1tL);
    cudaGetSymbolAddress((void**)&w2h, g_W2tH);
    cudaGetSymbolAddress((void**)&w2l, g_W2tL);
    cudaGetSymbolAddress((void**)&x2p, g_x2);
    cudaGetSymbolAddress((void**)&xwh, g_xwh);

    cudaFuncSetAttribute(gemm_tc<1>, cudaFuncAttributeMaxDynamicSharedMemorySize, SM_TOT);
    cudaFuncSetAttribute(gemm_tc<0>, cudaFuncAttributeMaxDynamicSharedMemorySize, SM_TOT);

    const int gblk = (n + 127) / 128;
    const int B_w  = ((K1 + 128) * 128 + 255) / 256;
    const int B_z  = (n + 255) / 256;

    cudaStream_t sB = cudaStreamPerThread;
    cudaEvent_t evF, evJ;
    cudaEventCreateWithFlags(&evF, cudaEventDisableTiming);
    cudaEventCreateWithFlags(&evJ, cudaEventDisableTiming);

    // 1) init: W split + zero everything
    k_init<<<B_w + B_z, 256>>>(W1, K1, W2, pooled, n, B_w);
    cudaEventRecord(evF, 0);
    cudaStreamWaitEvent(sB, evF, 0);

    // 2) persistent CSR on sB (hist -> prefix -> scatter), hidden under GEMM1
    k_csr<<<CSR_NB, 256, 0, sB>>>(src, dst, E, n);

    // 3) GEMM1 on stream 0 (concurrent with CSR)
    gemm_tc<1><<<gblk, 256, SM_TOT>>>(x, nullptr, n, K1, w1h, w1l, xwh,
                                      as1w, ad1w, g_as1_p, g_ad1_p, 4);

    cudaEventRecord(evJ, sB);
    cudaStreamWaitEvent(0, evJ, 0);

    // 4) gather1 (4th issued -> profiled)
    gather1<<<(n + 7) / 8, 256>>>(b1, n);
    // 5-8)
    gemm_tc<0><<<gblk, 256, SM_TOT>>>(nullptr, x2p, n, 128, w2h, w2l, xwh,
                                      as2w, ad2w, g_as2_p, g_ad2_p, 1);
    gather2<<<(n + 7) / 8, 256>>>(b2, Wq, qmask, ents, n);
    k_expsum_pool<<<512, 128>>>(ents, attn, pooled, n);
    k_norm<<<(n + 255) / 256, 256>>>(attn, pooled, n);

    cudaEventDestroy(evF);
    cudaEventDestroy(evJ);
}

// round 16
// speedup vs baseline: 1.0474x; 1.0004x over previous
#include <cuda_runtime.h>
#include <cuda_bf16.h>
#include <cuda_fp16.h>
#include <math.h>
#include <stdint.h>

#define NN_MAX 50000
#define E_MAX  800000
#define CSR_NB 296

// ---------------- scratch (device globals; no allocation) ----------------
__device__ __half   g_xwh[NN_MAX * 128];
__device__ __half   g_x2 [NN_MAX * 128];
__device__ float    g_as1 [NN_MAX * 4];
__device__ float    g_ad1 [NN_MAX * 4];
__device__ float    g_as2 [NN_MAX];
__device__ float    g_ad2 [NN_MAX];
__device__ float    g_logits[NN_MAX];
__device__ unsigned g_maxu[6];
__device__ float    g_sum [1];
__device__ int      g_cnt [1];
__device__ int      g_flag[1];
// CSR
__device__ int      g_deg   [NN_MAX];
__device__ int      g_rowptr[NN_MAX + 1];
__device__ int      g_cursor[NN_MAX];
__device__ int      g_col   [E_MAX + NN_MAX];
// W transposed hi/lo (fp16), [N=128][K] row-major
__device__ __half   g_W1tH[256 * 128];
__device__ __half   g_W1tL[256 * 128];
__device__ __half   g_W2tH[128 * 128];
__device__ __half   g_W2tL[128 * 128];

// ---------------- helpers ----------------
__device__ __forceinline__ unsigned ford(float f) {
    unsigned u = __float_as_uint(f);
    return (u & 0x80000000u) ? ~u : (u | 0x80000000u);
}
__device__ __forceinline__ float forddec(unsigned u) {
    return (u & 0x80000000u) ? __uint_as_float(u & 0x7fffffffu) : __uint_as_float(~u);
}
__device__ __forceinline__ float lrelu(float v) { return v > 0.f ? v : 0.2f * v; }
__device__ __forceinline__ float elu(float v)   { return v > 0.f ? v : expm1f(v); }

__device__ __forceinline__ uint32_t smem_u32(const void* p) {
    uint32_t a;
    asm("{ .reg .u64 t; cvta.to.shared.u64 t, %1; cvt.u32.u64 %0, t; }" : "=r"(a) : "l"(p));
    return a;
}
__device__ __forceinline__ void ldsm4(uint32_t a, uint32_t* r) {
    asm volatile("ldmatrix.sync.aligned.m8n8.x4.shared.b16 {%0,%1,%2,%3}, [%4];"
        : "=r"(r[0]), "=r"(r[1]), "=r"(r[2]), "=r"(r[3]) : "r"(a));
}
__device__ __forceinline__ void mma16816(float* c, const uint32_t* a, uint32_t b0, uint32_t b1) {
    asm volatile(
        "mma.sync.aligned.m16n8k16.row.col.f32.f16.f16.f32 "
        "{%0,%1,%2,%3}, {%4,%5,%6,%7}, {%8,%9}, {%0,%1,%2,%3};"
        : "+f"(c[0]), "+f"(c[1]), "+f"(c[2]), "+f"(c[3])
        : "r"(a[0]), "r"(a[1]), "r"(a[2]), "r"(a[3]), "r"(b0), "r"(b1));
}
// packed f32x2 helpers (Blackwell FFMA2)
__device__ __forceinline__ void ffma2(uint64_t& acc, uint64_t a, uint64_t b) {
    asm("fma.rn.f32x2 %0, %1, %2, %0;" : "+l"(acc) : "l"(a), "l"(b));
}
__device__ __forceinline__ uint64_t pack2(float x, float y) {
    uint64_t r;
    asm("mov.b64 %0, {%1, %2};" : "=l"(r) : "f"(x), "f"(y));
    return r;
}
__device__ __forceinline__ void unpack2(uint64_t p, float& x, float& y) {
    asm("mov.b64 {%0, %1}, %2;" : "=f"(x), "=f"(y) : "l"(p));
}
__device__ __forceinline__ uint64_t cvt2(uint32_t h2) {
    float2 f = __half22float2(*(__half2*)&h2);
    return pack2(f.x, f.y);
}

// ---------------- fused init: W fp16 hi/lo split + zeroing ----------------
__global__ void k_init(const float* __restrict__ W1, int K1, const float* __restrict__ W2,
                       float* __restrict__ pooled, int n, int B_w) {
    int b = blockIdx.x, tid = threadIdx.x;
    if (b < B_w) {
        int idx = b * 256 + tid;
        int n1 = K1 * 128;
        const float* W; __half *H, *L; int K;
        if (idx < n1) { W = W1; H = g_W1tH; L = g_W1tL; K = K1; }
        else { idx -= n1; if (idx >= 128 * 128) return; W = W2; H = g_W2tH; L = g_W2tL; K = 128; }
        int k = idx >> 7, nc = idx & 127;
        float v = W[idx];
        __half h = __float2half(v);
        H[(size_t)nc * K + k] = h;
        L[(size_t)nc * K + k] = __float2half(v - __half2float(h));
        return;
    }
    int gid = (b - B_w) * 256 + tid;
    if (gid < n) g_deg[gid] = 0;
    if (gid < 6) g_maxu[gid] = 0;
    if (gid == 6) g_sum[0] = 0.f;
    if (gid == 7) g_cnt[0] = 0;
    if (gid == 8) g_flag[0] = 0;
    if (gid >= 32 && gid < 160) pooled[gid - 32] = 0.f;
}

// ---------------- persistent CSR: hist -> prefix -> scatter ----------------
__global__ void __launch_bounds__(256, 8)
k_csr(const int* __restrict__ src, const int* __restrict__ dst, int E, int n) {
    int tid = threadIdx.x;
    int gid0 = blockIdx.x * 256 + tid;
    int gstride = CSR_NB * 256;
    int ET = E + n;

    for (int e = gid0; e < ET; e += gstride) {
        int d = (e < E) ? dst[e] : (e - E);
        atomicAdd(&g_deg[d], 1);
    }
    __syncthreads();
    __threadfence();

    if (blockIdx.x == 0) {
        if (tid == 0) {
            while (atomicAdd(&g_cnt[0], 0) < CSR_NB - 1) __nanosleep(100);
        }
        __syncthreads();
        __shared__ int sh[256];
        int chunk = (n + 255) / 256;
        int lo = tid * chunk, hi = min(lo + chunk, n);
        int part = 0;
        for (int i = lo; i < hi; i++) part += g_deg[i];
        sh[tid] = part;
        __syncthreads();
        for (int off = 1; off < 256; off <<= 1) {
            int v = (tid >= off) ? sh[tid - off] : 0;
            __syncthreads();
            sh[tid] += v;
            __syncthreads();
        }
        int base = (tid == 0) ? 0 : sh[tid - 1];
        for (int i = lo; i < hi; i++) {
            g_rowptr[i] = base;
            g_cursor[i] = base;
            base += g_deg[i];
        }
        if (tid == 0) g_rowptr[n] = sh[255];
        __threadfence();
        __syncthreads();
        if (tid == 0) atomicExch(&g_flag[0], 1);
    } else {
        if (tid == 0) {
            atomicAdd(&g_cnt[0], 1);
            while (atomicAdd(&g_flag[0], 0) == 0) __nanosleep(100);
        }
        __syncthreads();
    }

    for (int e = gid0; e < ET; e += gstride) {
        int s, d;
        if (e < E) { s = src[e]; d = dst[e]; } else { s = e - E; d = s; }
        int pos = atomicAdd(&g_cursor[d], 1);
        g_col[pos] = s;
    }
}

// ---------------- HMMA GEMM (R13): M128, 2-term fp16, occ 2; C fp16 --------
#define SSTR 72
#define SM_A  0
#define SM_BH 18432
#define SM_BL 36864
#define SM_TOT 55296

template<int MODE>
__global__ void __launch_bounds__(256, 2)
gemm_tc(const float* __restrict__ A, const __half* __restrict__ Ah,
        int M, int K,
        const __half* __restrict__ BtH, const __half* __restrict__ BtL,
        __half* __restrict__ Ch,
        const float* __restrict__ attS, const float* __restrict__ attD,
        float* __restrict__ asOut, float* __restrict__ adOut, int heads) {
    extern __shared__ __align__(128) char smem[];
    uint32_t sb = smem_u32(smem);
    int tid = threadIdx.x, lane = tid & 31, w = tid >> 5;
    int wm = w >> 1, wn = w & 1;
    int row0 = blockIdx.x * 128;
    int lr = lane & 15, lc = lane >> 4;

    float acc[16][4];
#pragma unroll
    for (int i = 0; i < 16; i++)
#pragma unroll
        for (int j = 0; j < 4; j++) acc[i][j] = 0.f;

    for (int k0 = 0; k0 < K; k0 += 64) {
        if (MODE == 1) {
#pragma unroll
            for (int i = 0; i < 8; i++) {
                int f = tid + i * 256;
                int r = f >> 4, c4 = (f & 15) << 2;
                float4 a = make_float4(0.f, 0.f, 0.f, 0.f);
                if (row0 + r < M)
                    a = *(const float4*)&A[(size_t)(row0 + r) * K + k0 + c4];
                __half2 p0 = __float22half2_rn(make_float2(a.x, a.y));
                __half2 p1 = __float22half2_rn(make_float2(a.z, a.w));
                uint32_t off = (uint32_t)(r * SSTR + c4) * 2;
                *(uint32_t*)(smem + SM_A + off)     = *(uint32_t*)&p0;
                *(uint32_t*)(smem + SM_A + off + 4) = *(uint32_t*)&p1;
            }
        } else {
#pragma unroll
            for (int i = 0; i < 4; i++) {
                int f = tid + i * 256;
                int r = f >> 3, u = (f & 7) << 3;
                uint4 z = make_uint4(0, 0, 0, 0);
                if (row0 + r < M)
                    z = *(const uint4*)&Ah[(size_t)(row0 + r) * K + k0 + u];
                *(uint4*)(smem + SM_A + (uint32_t)(r * SSTR + u) * 2) = z;
            }
        }
#pragma unroll
        for (int i = 0; i < 4; i++) {
            int f = tid + i * 256;
            int r = f >> 3, u = (f & 7) << 3;
            uint32_t off = (uint32_t)(r * SSTR + u) * 2;
            *(uint4*)(smem + SM_BH + off) = *(const uint4*)&BtH[(size_t)r * K + k0 + u];
            *(uint4*)(smem + SM_BL + off) = *(const uint4*)&BtL[(size_t)r * K + k0 + u];
        }
        __syncthreads();

#pragma unroll
        for (int ks = 0; ks < 4; ks++) {
            uint32_t aF[2][4];
#pragma unroll
            for (int mb = 0; mb < 2; mb++) {
                uint32_t off = (uint32_t)((wm * 32 + mb * 16 + lr) * SSTR + ks * 16 + lc * 8) * 2;
                ldsm4(sb + SM_A + off, aF[mb]);
            }
#pragma unroll
            for (int nbp = 0; nbp < 4; nbp++) {
                uint32_t offB = (uint32_t)((wn * 64 + nbp * 16 + lr) * SSTR + ks * 16 + lc * 8) * 2;
                uint32_t bh[4], bl[4];
                ldsm4(sb + SM_BH + offB, bh);
                ldsm4(sb + SM_BL + offB, bl);
#pragma unroll
                for (int mb = 0; mb < 2; mb++) {
                    float* c0 = acc[mb * 8 + nbp * 2];
                    float* c1 = acc[mb * 8 + nbp * 2 + 1];
                    mma16816(c0, aF[mb], bh[0], bh[2]);
                    mma16816(c0, aF[mb], bl[0], bl[2]);
                    mma16816(c1, aF[mb], bh[1], bh[3]);
                    mma16816(c1, aF[mb], bl[1], bl[3]);
                }
            }
        }
        __syncthreads();
    }

    // ---- epilogue ----
    float* sred = (float*)smem;
    unsigned* smax = (unsigned*)(smem + 2048);
    if (tid < 8) smax[tid] = 0u;
    __syncthreads();

    int g = lane >> 2, tq = lane & 3;
    float pS[8], pD[8];
#pragma unroll
    for (int i = 0; i < 8; i++) { pS[i] = 0.f; pD[i] = 0.f; }

#pragma unroll
    for (int mb = 0; mb < 2; mb++) {
#pragma unroll
        for (int nb = 0; nb < 8; nb++) {
            int col = wn * 64 + nb * 8 + tq * 2;
            float* c = acc[mb * 8 + nb];
            float s0 = attS[col], s1 = attS[col + 1];
            float d0 = attD[col], d1 = attD[col + 1];
            int sub = nb >> 2;
            pS[mb * 4 + sub]     += c[0] * s0 + c[1] * s1;
            pS[mb * 4 + 2 + sub] += c[2] * s0 + c[3] * s1;
            pD[mb * 4 + sub]     += c[0] * d0 + c[1] * d1;
            pD[mb * 4 + 2 + sub] += c[2] * d0 + c[3] * d1;
            int r = row0 + wm * 32 + mb * 16 + g;
            if (r < M) {
                __half2 p = __float22half2_rn(make_float2(c[0], c[1]));
                *(__half2*)&Ch[(size_t)r * 128 + col] = p;
            }
            if (r + 8 < M) {
                __half2 p = __float22half2_rn(make_float2(c[2], c[3]));
                *(__half2*)&Ch[(size_t)(r + 8) * 128 + col] = p;
            }
        }
    }
#pragma unroll
    for (int o = 1; o <= 2; o <<= 1) {
#pragma unroll
        for (int i = 0; i < 8; i++) {
            pS[i] += __shfl_xor_sync(0xffffffffu, pS[i], o);
            pD[i] += __shfl_xor_sync(0xffffffffu, pD[i], o);
        }
    }
    if (tq == 0) {
#pragma unroll
        for (int mb = 0; mb < 2; mb++) {
#pragma unroll
            for (int half = 0; half < 2; half++) {
                int rl = wm * 32 + mb * 16 + half * 8 + g;
                int r = row0 + rl;
                int i0 = mb * 4 + half * 2;
                if (heads == 4) {
                    if (r < M) {
                        asOut[r * 4 + wn * 2 + 0] = pS[i0 + 0];
                        asOut[r * 4 + wn * 2 + 1] = pS[i0 + 1];
                        adOut[r * 4 + wn * 2 + 0] = pD[i0 + 0];
                        adOut[r * 4 + wn * 2 + 1] = pD[i0 + 1];
                        atomicMax(&smax[wn * 2 + 0], ford(pS[i0 + 0]));
                        atomicMax(&smax[wn * 2 + 1], ford(pS[i0 + 1]));
                    }
                } else {
                    sred[rl * 4 + wn * 2 + 0] = pS[i0] + pS[i0 + 1];
                    sred[rl * 4 + wn * 2 + 1] = pD[i0] + pD[i0 + 1];
                }
            }
        }
    }
    __syncthreads();
    if (heads == 4) {
        if (tid < 4) atomicMax(&g_maxu[tid], smax[tid]);
    } else {
        if (tid < 128) {
            int r = row0 + tid;
            if (r < M) {
                float S = sred[tid * 4 + 0] + sred[tid * 4 + 2];
                float D = sred[tid * 4 + 1] + sred[tid * 4 + 3];
                asOut[r] = S;
                adOut[r] = D;
                atomicMax(&smax[0], ford(S));
            }
        }
        __syncthreads();
        if (tid == 0) atomicMax(&g_maxu[4], smax[0]);
    }
}

// ---------------- layer-1 gather: packed FFMA2, 2 edges/warp ----------------
__global__ void gather1(const float* __restrict__ b1, int n) {
    int d = (blockIdx.x * blockDim.x + threadIdx.x) >> 5;
    int lane = threadIdx.x & 31;
    if (d >= n) return;
    int grp = lane >> 4, l = lane & 15;
    int h = l >> 2;
    int r0 = g_rowptr[d], r1 = g_rowptr[d + 1];
    float ad_h = g_ad1[d * 4 + h];
    float m_h = lrelu(forddec(g_maxu[h]) + ad_h);
    const char* xw = (const char*)g_xwh;
    uint32_t loff = (uint32_t)l << 4;

    uint64_t a01 = 0, a23 = 0, a45 = 0, a67 = 0;
    float den = 0.f;

    int e = r0 + grp;
    for (; e + 2 < r1; e += 4) {
        int s0 = g_col[e], s1 = g_col[e + 2];
        float v0 = g_as1[s0 * 4 + h], v1 = g_as1[s1 * 4 + h];
        uint4 q0 = *(const uint4*)(xw + (((uint32_t)s0 << 8) + loff));
        uint4 q1 = *(const uint4*)(xw + (((uint32_t)s1 << 8) + loff));
        float w0 = __expf(lrelu(v0 + ad_h) - m_h);
        float w1 = __expf(lrelu(v1 + ad_h) - m_h);
        uint64_t wp0 = pack2(w0, w0), wp1 = pack2(w1, w1);
        den += w0 + w1;
        ffma2(a01, cvt2(q0.x), wp0); ffma2(a01, cvt2(q1.x), wp1);
        ffma2(a23, cvt2(q0.y), wp0); ffma2(a23, cvt2(q1.y), wp1);
        ffma2(a45, cvt2(q0.z), wp0); ffma2(a45, cvt2(q1.z), wp1);
        ffma2(a67, cvt2(q0.w), wp0); ffma2(a67, cvt2(q1.w), wp1);
    }
    if (e < r1) {
        int s0 = g_col[e];
        float w0 = __expf(lrelu(g_as1[s0 * 4 + h] + ad_h) - m_h);
        uint4 q0 = *(const uint4*)(xw + (((uint32_t)s0 << 8) + loff));
        uint64_t wp0 = pack2(w0, w0);
        den += w0;
        ffma2(a01, cvt2(q0.x), wp0);
        ffma2(a23, cvt2(q0.y), wp0);
        ffma2(a45, cvt2(q0.z), wp0);
        ffma2(a67, cvt2(q0.w), wp0);
    }
    float acc[8];
    unpack2(a01, acc[0], acc[1]);
    unpack2(a23, acc[2], acc[3]);
    unpack2(a45, acc[4], acc[5]);
    unpack2(a67, acc[6], acc[7]);
#pragma unroll
    for (int j = 0; j < 8; j++) acc[j] += __shfl_xor_sync(0xffffffffu, acc[j], 16);
    den += __shfl_xor_sync(0xffffffffu, den, 16);

    if (grp == 0) {
        float inv = 1.f / (den + 1e-16f);
        __half hv[8];
#pragma unroll
        for (int j = 0; j < 8; j++)
            hv[j] = __float2half(elu(acc[j] * inv + b1[l * 8 + j]));
        *(uint4*)&g_x2[(size_t)d * 128 + l * 8] = *(uint4*)hv;
    }
}

// ---------------- layer-2 gather: packed FFMA2, fused ents+logits ----------
__global__ void gather2(const float* __restrict__ b2, const float* __restrict__ Wq,
                        const int* __restrict__ qmask, float* __restrict__ ents, int n) {
    int d = (blockIdx.x * blockDim.x + threadIdx.x) >> 5;
    int lane = threadIdx.x & 31;
    if (d >= n) return;
    int grp = lane >> 4, l = lane & 15;
    int r0 = g_rowptr[d], r1 = g_rowptr[d + 1];
    float ad = g_ad2[d];
    float mx = lrelu(forddec(g_maxu[4]) + ad);
    const char* xw = (const char*)g_xwh;
    uint32_t loff = (uint32_t)l << 4;

    uint64_t a01 = 0, a23 = 0, a45 = 0, a67 = 0;
    float den = 0.f;

    int e = r0 + grp;
    for (; e + 2 < r1; e += 4) {
        int s0 = g_col[e], s1 = g_col[e + 2];
        float v0 = g_as2[s0], v1 = g_as2[s1];
        uint4 q0 = *(const uint4*)(xw + (((uint32_t)s0 << 8) + loff));
        uint4 q1 = *(const uint4*)(xw + (((uint32_t)s1 << 8) + loff));
        float w0 = __expf(lrelu(v0 + ad) - mx);
        float w1 = __expf(lrelu(v1 + ad) - mx);
        uint64_t wp0 = pack2(w0, w0), wp1 = pack2(w1, w1);
        den += w0 + w1;
        ffma2(a01, cvt2(q0.x), wp0); ffma2(a01, cvt2(q1.x), wp1);
        ffma2(a23, cvt2(q0.y), wp0); ffma2(a23, cvt2(q1.y), wp1);
        ffma2(a45, cvt2(q0.z), wp0); ffma2(a45, cvt2(q1.z), wp1);
        ffma2(a67, cvt2(q0.w), wp0); ffma2(a67, cvt2(q1.w), wp1);
    }
    if (e < r1) {
        int s0 = g_col[e];
        float w0 = __expf(lrelu(g_as2[s0] + ad) - mx);
        uint4 q0 = *(const uint4*)(xw + (((uint32_t)s0 << 8) + loff));
        uint64_t wp0 = pack2(w0, w0);
        den += w0;
        ffma2(a01, cvt2(q0.x), wp0);
        ffma2(a23, cvt2(q0.y), wp0);
        ffma2(a45, cvt2(q0.z), wp0);
        ffma2(a67, cvt2(q0.w), wp0);
    }
    float acc[8];
    unpack2(a01, acc[0], acc[1]);
    unpack2(a23, acc[2], acc[3]);
    unpack2(a45, acc[4], acc[5]);
    unpack2(a67, acc[6], acc[7]);
#pragma unroll
    for (int j = 0; j < 8; j++) acc[j] += __shfl_xor_sync(0xffffffffu, acc[j], 16);
    den += __shfl_xor_sync(0xffffffffu, den, 16);

    float inv = 1.f / (den + 1e-16f);
    float v[8];
    float dotp = 0.f;
#pragma unroll
    for (int j = 0; j < 8; j++) {
        v[j] = elu(acc[j] * inv + b2[l * 8 + j]);
        dotp += v[j] * Wq[l * 8 + j];
    }
    if (grp == 0) {
        float4 o0 = make_float4(v[0], v[1], v[2], v[3]);
        float4 o1 = make_float4(v[4], v[5], v[6], v[7]);
        *(float4*)&ents[(size_t)d * 128 + l * 8]     = o0;
        *(float4*)&ents[(size_t)d * 128 + l * 8 + 4] = o1;
    }
#pragma unroll
    for (int o = 8; o; o >>= 1) dotp += __shfl_xor_sync(0xffffffffu, dotp, o);
    if (lane == 0) {
        float logit = dotp + ((float)qmask[d] - 1.f) * 1e9f;
        g_logits[d] = logit;
        atomicMax(&g_maxu[5], ford(logit));
    }
}

// ---------------- fused expsum + pooled accumulation ----------------
__global__ void k_expsum_pool(const float* __restrict__ ents, float* __restrict__ attn,
                              float* __restrict__ pooled, int n) {
    int t = threadIdx.x;
    float M = forddec(g_maxu[5]);
    float acc = 0.f, se = 0.f;
    for (int nn = blockIdx.x; nn < n; nn += gridDim.x) {
        float e = __expf(g_logits[nn] - M);
        if (t == 0) attn[nn] = e;
        se += e;
        acc += e * ents[(size_t)nn * 128 + t];
    }
    atomicAdd(&pooled[t], acc);
    if (t == 0) atomicAdd(&g_sum[0], se);
}

__global__ void k_norm(float* __restrict__ attn, float* __restrict__ pooled, int n) {
    float inv = 1.f / g_sum[0];
    for (int i = blockIdx.x * blockDim.x + threadIdx.x; i < n; i += gridDim.x * blockDim.x) {
        attn[i] *= inv;
        if (i < 128) pooled[i] *= inv;
    }
}

// ---------------- launch ----------------
extern "C" void kernel_launch(void* const* d_in, const int* in_sizes, int n_in,
                              void* d_out, int out_size) {
    const float* x     = (const float*)d_in[0];
    const int*   eidx  = (const int*)  d_in[1];
    const int*   qmask = (const int*)  d_in[3];
    const float* W1    = (const float*)d_in[5];
    const float* as1w  = (const float*)d_in[6];
    const float* ad1w  = (const float*)d_in[7];
    const float* b1    = (const float*)d_in[8];
    const float* W2    = (const float*)d_in[9];
    const float* as2w  = (const float*)d_in[10];
    const float* ad2w  = (const float*)d_in[11];
    const float* b2    = (const float*)d_in[12];
    const float* Wq    = (const float*)d_in[13];

    const int n = in_sizes[3];
    const int E = in_sizes[1] / 2;
    const int K1 = in_sizes[0] / n;

    const int* src = eidx;
    const int* dst = eidx + E;

    float* out    = (float*)d_out;
    float* pooled = out;
    float* ents   = out + 128;
    float* attn   = out + 128 + (size_t)n * 128;

    float *g_as1_p, *g_ad1_p, *g_as2_p, *g_ad2_p;
    cudaGetSymbolAddress((void**)&g_as1_p, g_as1);
    cudaGetSymbolAddress((void**)&g_ad1_p, g_ad1);
    cudaGetSymbolAddress((void**)&g_as2_p, g_as2);
    cudaGetSymbolAddress((void**)&g_ad2_p, g_ad2);
    __half *w1h, *w1l, *w2h, *w2l, *x2p, *xwh;
    cudaGetSymbolAddress((void**)&w1h, g_W1tH);
    cudaGetSymbolAddress((void**)&w1l, g_W1tL);
    cudaGetSymbolAddress((void**)&w2h, g_W2tH);
    cudaGetSymbolAddress((void**)&w2l, g_W2tL);
    cudaGetSymbolAddress((void**)&x2p, g_x2);
    cudaGetSymbolAddress((void**)&xwh, g_xwh);

    cudaFuncSetAttribute(gemm_tc<1>, cudaFuncAttributeMaxDynamicSharedMemorySize, SM_TOT);
    cudaFuncSetAttribute(gemm_tc<0>, cudaFuncAttributeMaxDynamicSharedMemorySize, SM_TOT);

    const int gblk = (n + 127) / 128;
    const int B_w  = ((K1 + 128) * 128 + 255) / 256;
    const int B_z  = (n + 255) / 256;

    cudaStream_t sB = cudaStreamPerThread;
    cudaEvent_t evF, evJ;
    cudaEventCreateWithFlags(&evF, cudaEventDisableTiming);
    cudaEventCreateWithFlags(&evJ, cudaEventDisableTiming);

    k_init<<<B_w + B_z, 256>>>(W1, K1, W2, pooled, n, B_w);
    cudaEventRecord(evF, 0);
    cudaStreamWaitEvent(sB, evF, 0);

    k_csr<<<CSR_NB, 256, 0, sB>>>(src, dst, E, n);

    gemm_tc<1><<<gblk, 256, SM_TOT>>>(x, nullptr, n, K1, w1h, w1l, xwh,
                                      as1w, ad1w, g_as1_p, g_ad1_p, 4);

    cudaEventRecord(evJ, sB);
    cudaStreamWaitEvent(0, evJ, 0);

    gather1<<<(n + 7) / 8, 256>>>(b1, n);
    gemm_tc<0><<<gblk, 256, SM_TOT>>>(nullptr, x2p, n, 128, w2h, w2l, xwh,
                                      as2w, ad2w, g_as2_p, g_ad2_p, 1);
    gather2<<<(n + 7) / 8, 256>>>(b2, Wq, qmask, ents, n);
    k_expsum_pool<<<512, 128>>>(ents, attn, pooled, n);
    k_norm<<<(n + 255) / 256, 256>>>(attn, pooled, n);

    cudaEventDestroy(evF);
    cudaEventDestroy(evJ);
}